// round 3
// baseline (speedup 1.0000x reference)
#include <cuda_runtime.h>
#include <float.h>

// Problem constants (fixed by reference setup_inputs)
#define N_PTS 8192
#define C_CH  256
#define KNN   16

// ---------------- scratch (device globals; no allocation allowed) ----------
__device__ float4 g_xyzs[N_PTS];            // x,y,z, |p|^2
__device__ int    g_idx[N_PTS * KNN];       // knn indices
__device__ float  g_theta[N_PTS * C_CH];    // feats @ theta_w + b
__device__ float  g_phi  [N_PTS * C_CH];    // feats @ phi_w + b
__device__ float  g_gv   [N_PTS * C_CH];    // feats @ g_w + b
__device__ float  g_y    [N_PTS * C_CH];    // attention output

// ---------------------------------------------------------------------------
// 1) pack coords + squared norms (matches reference: sq = x*x + y*y + z*z)
// ---------------------------------------------------------------------------
__global__ __launch_bounds__(256) void prep_kernel(const float* __restrict__ coords) {
    int i = blockIdx.x * blockDim.x + threadIdx.x;
    if (i < N_PTS) {
        float x = coords[i * 3 + 0], y = coords[i * 3 + 1], z = coords[i * 3 + 2];
        g_xyzs[i] = make_float4(x, y, z, x * x + y * y + z * z);
    }
}

// ---------------------------------------------------------------------------
// 2) KNN: one block per query point. Distances into shared, then 16x argmin
//    with per-thread cached local minima (winner-only rescan).
//    d2 = sq_i + sq_j - 2*dot  (same formula as reference -> same neighbor set)
// ---------------------------------------------------------------------------
__global__ __launch_bounds__(256) void knn_kernel() {
    __shared__ float sd[N_PTS];       // 32 KB
    __shared__ float wmin[8];
    __shared__ int   warg[8];
    __shared__ int   s_win;

    const int i   = blockIdx.x;
    const int tid = threadIdx.x;
    const float4 q = g_xyzs[i];

    float lmin = FLT_MAX;
    int   larg = 0x7fffffff;
    for (int j = tid; j < N_PTS; j += 256) {
        float4 p = g_xyzs[j];
        float d = q.w + p.w - 2.0f * (q.x * p.x + q.y * p.y + q.z * p.z);
        sd[j] = d;
        if (d < lmin || (d == lmin && j < larg)) { lmin = d; larg = j; }
    }
    __syncthreads();

    const int lane = tid & 31, wid = tid >> 5;
    for (int it = 0; it < KNN; it++) {
        // warp-level (val, idx) argmin reduce of per-thread cached minima
        float v = lmin; int a = larg;
        #pragma unroll
        for (int off = 16; off > 0; off >>= 1) {
            float ov = __shfl_down_sync(0xffffffffu, v, off);
            int   oa = __shfl_down_sync(0xffffffffu, a, off);
            if (ov < v || (ov == v && oa < a)) { v = ov; a = oa; }
        }
        if (lane == 0) { wmin[wid] = v; warg[wid] = a; }
        __syncthreads();
        if (tid == 0) {
            float bv = wmin[0]; int ba = warg[0];
            #pragma unroll
            for (int w = 1; w < 8; w++)
                if (wmin[w] < bv || (wmin[w] == bv && warg[w] < ba)) { bv = wmin[w]; ba = warg[w]; }
            s_win = ba;
            g_idx[i * KNN + it] = ba;
        }
        __syncthreads();
        const int wa = s_win;
        if ((wa & 255) == tid) {           // owner thread removes & rescans its 32
            sd[wa] = FLT_MAX;
            lmin = FLT_MAX; larg = 0x7fffffff;
            for (int j = tid; j < N_PTS; j += 256) {
                float d = sd[j];
                if (d < lmin || (d == lmin && j < larg)) { lmin = d; larg = j; }
            }
        }
        // (wmin of next iter is written after this point's implicit ordering;
        //  s_win for next iter is written after next __syncthreads)
    }
}

// ---------------------------------------------------------------------------
// 3) generic C[M,N] = A[M,256] @ B[256,N] + bias (+ residual)
//    M=8192, N=256, K=256. 64x64 tile, BK=16, 256 threads, 4x4 microtile.
// ---------------------------------------------------------------------------
__global__ __launch_bounds__(256) void gemm64_kernel(const float* __restrict__ A,
                                                     const float* __restrict__ B,
                                                     const float* __restrict__ bias,
                                                     const float* __restrict__ resid,
                                                     float* __restrict__ C) {
    __shared__ float As[16][65];   // [k][row], padded
    __shared__ float Bs[16][64];   // [k][col]

    const int tid  = threadIdx.x;
    const int row0 = blockIdx.y * 64;
    const int col0 = blockIdx.x * 64;
    const int tx = tid & 15, ty = tid >> 4;
    const int ar = tid >> 2, ak = (tid & 3) * 4;
    const int br = tid >> 4, bc = (tid & 15) * 4;

    float acc[4][4];
    #pragma unroll
    for (int r = 0; r < 4; r++)
        #pragma unroll
        for (int c = 0; c < 4; c++) acc[r][c] = 0.0f;

    for (int k0 = 0; k0 < 256; k0 += 16) {
        float4 av = *(const float4*)&A[(row0 + ar) * 256 + k0 + ak];
        float4 bv = *(const float4*)&B[(k0 + br) * 256 + col0 + bc];
        As[ak + 0][ar] = av.x; As[ak + 1][ar] = av.y;
        As[ak + 2][ar] = av.z; As[ak + 3][ar] = av.w;
        *(float4*)&Bs[br][bc] = bv;
        __syncthreads();
        #pragma unroll
        for (int kk = 0; kk < 16; kk++) {
            float a0 = As[kk][ty * 4 + 0], a1 = As[kk][ty * 4 + 1];
            float a2 = As[kk][ty * 4 + 2], a3 = As[kk][ty * 4 + 3];
            float4 b = *(float4*)&Bs[kk][tx * 4];
            acc[0][0] = fmaf(a0, b.x, acc[0][0]); acc[0][1] = fmaf(a0, b.y, acc[0][1]);
            acc[0][2] = fmaf(a0, b.z, acc[0][2]); acc[0][3] = fmaf(a0, b.w, acc[0][3]);
            acc[1][0] = fmaf(a1, b.x, acc[1][0]); acc[1][1] = fmaf(a1, b.y, acc[1][1]);
            acc[1][2] = fmaf(a1, b.z, acc[1][2]); acc[1][3] = fmaf(a1, b.w, acc[1][3]);
            acc[2][0] = fmaf(a2, b.x, acc[2][0]); acc[2][1] = fmaf(a2, b.y, acc[2][1]);
            acc[2][2] = fmaf(a2, b.z, acc[2][2]); acc[2][3] = fmaf(a2, b.w, acc[2][3]);
            acc[3][0] = fmaf(a3, b.x, acc[3][0]); acc[3][1] = fmaf(a3, b.y, acc[3][1]);
            acc[3][2] = fmaf(a3, b.z, acc[3][2]); acc[3][3] = fmaf(a3, b.w, acc[3][3]);
        }
        __syncthreads();
    }

    #pragma unroll
    for (int r = 0; r < 4; r++) {
        const int row = row0 + ty * 4 + r;
        #pragma unroll
        for (int c = 0; c < 4; c++) {
            const int col = col0 + tx * 4 + c;
            float v = acc[r][c] + bias[col];
            if (resid) v += resid[row * 256 + col];
            C[row * 256 + col] = v;
        }
    }
}

// ---------------------------------------------------------------------------
// 4) fused pe-MLP + delta-features + softmax(K) + y reduction.
//    One block per point. 256 threads.
//    pe[k][c] = relu(dc[k] @ w1 + b1) @ w2 + b2
//    df = pe * (theta_i - phi_nn + 1) / 16 ; softmax over k ; y = sum sim*g
// ---------------------------------------------------------------------------
__global__ __launch_bounds__(256) void attn_kernel(const float* __restrict__ coords,
                                                   const float* __restrict__ w1,
                                                   const float* __restrict__ b1,
                                                   const float* __restrict__ w2,
                                                   const float* __restrict__ b2) {
    __shared__ float sh[16 * 256];       // hidden layer h[k][c]  (16 KB)
    __shared__ float sdf[256 * 17];      // df[c][k], pad 17      (17 KB)
    __shared__ int   sidx[16];
    __shared__ float sdc[16 * 3];

    const int i = blockIdx.x, tid = threadIdx.x;

    if (tid < 16) sidx[tid] = g_idx[i * KNN + tid];
    __syncthreads();
    if (tid < 48) {
        const int k = tid / 3, d = tid - k * 3;
        sdc[tid] = coords[sidx[k] * 3 + d] - coords[i * 3 + d];
    }
    __syncthreads();

    // layer 1: h[k][tid] = relu(dc[k] . w1[:,tid] + b1[tid]); weights in regs
    {
        const float w10 = w1[tid], w11 = w1[256 + tid], w12 = w1[512 + tid];
        const float bb  = b1[tid];
        #pragma unroll
        for (int k = 0; k < 16; k++) {
            float v = fmaf(sdc[k * 3 + 2], w12,
                      fmaf(sdc[k * 3 + 1], w11,
                      fmaf(sdc[k * 3 + 0], w10, bb)));
            sh[k * 256 + tid] = fmaxf(v, 0.0f);
        }
    }
    __syncthreads();

    // layer 2 GEMM: 16(k) x 256(c) x 256(j). thread = (4 c, 4 k) microtile.
    const int cg = tid & 63, kg = tid >> 6;
    const int c0 = cg * 4, k0 = kg * 4;
    const float4 bb2 = *(const float4*)&b2[c0];
    float acc[4][4];
    #pragma unroll
    for (int kk = 0; kk < 4; kk++) {
        acc[kk][0] = bb2.x; acc[kk][1] = bb2.y; acc[kk][2] = bb2.z; acc[kk][3] = bb2.w;
    }
    const float* hp = &sh[k0 * 256];
    #pragma unroll 4
    for (int j = 0; j < 256; j++) {
        const float4 w = *(const float4*)&w2[j * 256 + c0];
        const float h0 = hp[j], h1 = hp[256 + j], h2 = hp[512 + j], h3 = hp[768 + j];
        acc[0][0] = fmaf(h0, w.x, acc[0][0]); acc[0][1] = fmaf(h0, w.y, acc[0][1]);
        acc[0][2] = fmaf(h0, w.z, acc[0][2]); acc[0][3] = fmaf(h0, w.w, acc[0][3]);
        acc[1][0] = fmaf(h1, w.x, acc[1][0]); acc[1][1] = fmaf(h1, w.y, acc[1][1]);
        acc[1][2] = fmaf(h1, w.z, acc[1][2]); acc[1][3] = fmaf(h1, w.w, acc[1][3]);
        acc[2][0] = fmaf(h2, w.x, acc[2][0]); acc[2][1] = fmaf(h2, w.y, acc[2][1]);
        acc[2][2] = fmaf(h2, w.z, acc[2][2]); acc[2][3] = fmaf(h2, w.w, acc[2][3]);
        acc[3][0] = fmaf(h3, w.x, acc[3][0]); acc[3][1] = fmaf(h3, w.y, acc[3][1]);
        acc[3][2] = fmaf(h3, w.z, acc[3][2]); acc[3][3] = fmaf(h3, w.w, acc[3][3]);
    }

    // delta features -> shared [c][k] (pad 17 for conflict-free reads by k)
    {
        const float4 th = *(const float4*)&g_theta[i * 256 + c0];
        #pragma unroll
        for (int kk = 0; kk < 4; kk++) {
            const int nn = sidx[k0 + kk];
            const float4 ph = *(const float4*)&g_phi[nn * 256 + c0];
            sdf[(c0 + 0) * 17 + k0 + kk] = acc[kk][0] * (th.x - ph.x + 1.0f) * 0.0625f;
            sdf[(c0 + 1) * 17 + k0 + kk] = acc[kk][1] * (th.y - ph.y + 1.0f) * 0.0625f;
            sdf[(c0 + 2) * 17 + k0 + kk] = acc[kk][2] * (th.z - ph.z + 1.0f) * 0.0625f;
            sdf[(c0 + 3) * 17 + k0 + kk] = acc[kk][3] * (th.w - ph.w + 1.0f) * 0.0625f;
        }
    }
    __syncthreads();

    // softmax over K + weighted sum with g_feats; thread = one channel
    {
        const int c = tid;
        float m = -FLT_MAX;
        #pragma unroll
        for (int k = 0; k < 16; k++) m = fmaxf(m, sdf[c * 17 + k]);
        float e[16];
        float s = 0.0f;
        #pragma unroll
        for (int k = 0; k < 16; k++) { e[k] = __expf(sdf[c * 17 + k] - m); s += e[k]; }
        const float inv = 1.0f / s;
        float a = 0.0f;
        #pragma unroll
        for (int k = 0; k < 16; k++) a = fmaf(e[k], g_gv[sidx[k] * 256 + c], a);
        g_y[i * 256 + c] = a * inv;
    }
}

// ---------------------------------------------------------------------------
extern "C" void kernel_launch(void* const* d_in, const int* in_sizes, int n_in,
                              void* d_out, int out_size) {
    const float* coords  = (const float*)d_in[0];
    const float* feats   = (const float*)d_in[1];
    const float* theta_w = (const float*)d_in[2];
    const float* theta_b = (const float*)d_in[3];
    const float* phi_w   = (const float*)d_in[4];
    const float* phi_b   = (const float*)d_in[5];
    const float* g_w     = (const float*)d_in[6];
    const float* g_b     = (const float*)d_in[7];
    const float* pe_w1   = (const float*)d_in[8];
    const float* pe_b1   = (const float*)d_in[9];
    const float* pe_w2   = (const float*)d_in[10];
    const float* pe_b2   = (const float*)d_in[11];
    const float* W_w     = (const float*)d_in[12];
    const float* W_b     = (const float*)d_in[13];
    float* out = (float*)d_out;

    float *p_theta, *p_phi, *p_gv, *p_y;
    cudaGetSymbolAddress((void**)&p_theta, g_theta);
    cudaGetSymbolAddress((void**)&p_phi,   g_phi);
    cudaGetSymbolAddress((void**)&p_gv,    g_gv);
    cudaGetSymbolAddress((void**)&p_y,     g_y);

    prep_kernel<<<(N_PTS + 255) / 256, 256>>>(coords);
    knn_kernel<<<N_PTS, 256>>>();

    dim3 ggrid(C_CH / 64, N_PTS / 64);
    gemm64_kernel<<<ggrid, 256>>>(feats, theta_w, theta_b, nullptr, p_theta);
    gemm64_kernel<<<ggrid, 256>>>(feats, phi_w,   phi_b,   nullptr, p_phi);
    gemm64_kernel<<<ggrid, 256>>>(feats, g_w,     g_b,     nullptr, p_gv);

    attn_kernel<<<N_PTS, 256>>>(coords, pe_w1, pe_b1, pe_w2, pe_b2);

    gemm64_kernel<<<ggrid, 256>>>(p_y, W_w, W_b, feats, out);
}

// round 4
// speedup vs baseline: 1.0392x; 1.0392x over previous
#include <cuda_runtime.h>
#include <float.h>

// Problem constants (fixed by reference setup_inputs)
#define N_PTS 8192
#define C_CH  256
#define KNN   16

typedef unsigned long long u64;

// ---------------- packed-fp32 (FFMA2) helpers --------------------------------
__device__ __forceinline__ void fma2(u64 &acc, u64 a, u64 b) {
    asm("fma.rn.f32x2 %0, %1, %2, %0;" : "+l"(acc) : "l"(a), "l"(b));
}
__device__ __forceinline__ u64 bcast2(float v) {
    u64 r;
    asm("mov.b64 %0, {%1, %2};" : "=l"(r) : "f"(v), "f"(v));
    return r;
}
__device__ __forceinline__ void unpack2(u64 v, float &lo, float &hi) {
    asm("mov.b64 {%0, %1}, %2;" : "=f"(lo), "=f"(hi) : "l"(v));
}

// ---------------- scratch (device globals; no allocation allowed) ----------
__device__ float4 g_xyzs[N_PTS];            // x,y,z, |p|^2
__device__ int    g_idx[N_PTS * KNN];       // knn indices
__device__ float  g_theta[N_PTS * C_CH];    // feats @ theta_w + b
__device__ float  g_phi  [N_PTS * C_CH];    // feats @ phi_w + b
__device__ float  g_gv   [N_PTS * C_CH];    // feats @ g_w + b
__device__ float  g_y    [N_PTS * C_CH];    // attention output

// ---------------------------------------------------------------------------
// 1) pack coords + squared norms (matches reference: sq = x*x + y*y + z*z)
// ---------------------------------------------------------------------------
__global__ __launch_bounds__(256) void prep_kernel(const float* __restrict__ coords) {
    int i = blockIdx.x * blockDim.x + threadIdx.x;
    if (i < N_PTS) {
        float x = coords[i * 3 + 0], y = coords[i * 3 + 1], z = coords[i * 3 + 2];
        g_xyzs[i] = make_float4(x, y, z, x * x + y * y + z * z);
    }
}

// ---------------------------------------------------------------------------
// 2) KNN: one block per query point. Distances into shared, then 16x argmin
//    with per-thread cached local minima (winner-only rescan).
//    d2 = sq_i + sq_j - 2*dot  (same formula as reference -> same neighbor set)
// ---------------------------------------------------------------------------
__global__ __launch_bounds__(256) void knn_kernel() {
    __shared__ float sd[N_PTS];       // 32 KB
    __shared__ float wmin[8];
    __shared__ int   warg[8];
    __shared__ int   s_win;

    const int i   = blockIdx.x;
    const int tid = threadIdx.x;
    const float4 q = g_xyzs[i];

    float lmin = FLT_MAX;
    int   larg = 0x7fffffff;
    for (int j = tid; j < N_PTS; j += 256) {
        float4 p = g_xyzs[j];
        float d = q.w + p.w - 2.0f * (q.x * p.x + q.y * p.y + q.z * p.z);
        sd[j] = d;
        if (d < lmin || (d == lmin && j < larg)) { lmin = d; larg = j; }
    }
    __syncthreads();

    const int lane = tid & 31, wid = tid >> 5;
    for (int it = 0; it < KNN; it++) {
        // warp-level (val, idx) argmin reduce of per-thread cached minima
        float v = lmin; int a = larg;
        #pragma unroll
        for (int off = 16; off > 0; off >>= 1) {
            float ov = __shfl_down_sync(0xffffffffu, v, off);
            int   oa = __shfl_down_sync(0xffffffffu, a, off);
            if (ov < v || (ov == v && oa < a)) { v = ov; a = oa; }
        }
        if (lane == 0) { wmin[wid] = v; warg[wid] = a; }
        __syncthreads();
        if (tid == 0) {
            float bv = wmin[0]; int ba = warg[0];
            #pragma unroll
            for (int w = 1; w < 8; w++)
                if (wmin[w] < bv || (wmin[w] == bv && warg[w] < ba)) { bv = wmin[w]; ba = warg[w]; }
            s_win = ba;
            g_idx[i * KNN + it] = ba;
        }
        __syncthreads();
        const int wa = s_win;
        if ((wa & 255) == tid) {           // owner thread removes & rescans its 32
            sd[wa] = FLT_MAX;
            lmin = FLT_MAX; larg = 0x7fffffff;
            for (int j = tid; j < N_PTS; j += 256) {
                float d = sd[j];
                if (d < lmin || (d == lmin && j < larg)) { lmin = d; larg = j; }
            }
        }
    }
}

// ---------------------------------------------------------------------------
// 3) generic C[M,N] = A[M,256] @ B[256,N] + bias (+ residual)
//    M=8192, N=256, K=256. 64x64 tile, BK=16, 256 threads, 4x4 microtile.
//    FFMA2 (fma.rn.f32x2) on column pairs.
// ---------------------------------------------------------------------------
__global__ __launch_bounds__(256) void gemm64_kernel(const float* __restrict__ A,
                                                     const float* __restrict__ B,
                                                     const float* __restrict__ bias,
                                                     const float* __restrict__ resid,
                                                     float* __restrict__ C) {
    __shared__ float As[16][65];   // [k][row], padded
    __shared__ float Bs[16][64];   // [k][col]

    const int tid  = threadIdx.x;
    const int row0 = blockIdx.y * 64;
    const int col0 = blockIdx.x * 64;
    const int tx = tid & 15, ty = tid >> 4;
    const int ar = tid >> 2, ak = (tid & 3) * 4;
    const int br = tid >> 4, bc = (tid & 15) * 4;

    u64 acc[4][2];                 // [row][col-pair]
    #pragma unroll
    for (int r = 0; r < 4; r++) { acc[r][0] = 0ull; acc[r][1] = 0ull; }

    for (int k0 = 0; k0 < 256; k0 += 16) {
        float4 av = *(const float4*)&A[(row0 + ar) * 256 + k0 + ak];
        float4 bv = *(const float4*)&B[(k0 + br) * 256 + col0 + bc];
        As[ak + 0][ar] = av.x; As[ak + 1][ar] = av.y;
        As[ak + 2][ar] = av.z; As[ak + 3][ar] = av.w;
        *(float4*)&Bs[br][bc] = bv;
        __syncthreads();
        #pragma unroll
        for (int kk = 0; kk < 16; kk++) {
            const u64 aa0 = bcast2(As[kk][ty * 4 + 0]);
            const u64 aa1 = bcast2(As[kk][ty * 4 + 1]);
            const u64 aa2 = bcast2(As[kk][ty * 4 + 2]);
            const u64 aa3 = bcast2(As[kk][ty * 4 + 3]);
            const ulonglong2 b = *(const ulonglong2*)&Bs[kk][tx * 4];
            fma2(acc[0][0], aa0, b.x); fma2(acc[0][1], aa0, b.y);
            fma2(acc[1][0], aa1, b.x); fma2(acc[1][1], aa1, b.y);
            fma2(acc[2][0], aa2, b.x); fma2(acc[2][1], aa2, b.y);
            fma2(acc[3][0], aa3, b.x); fma2(acc[3][1], aa3, b.y);
        }
        __syncthreads();
    }

    #pragma unroll
    for (int r = 0; r < 4; r++) {
        const int row = row0 + ty * 4 + r;
        const int col = col0 + tx * 4;
        float v0, v1, v2, v3;
        unpack2(acc[r][0], v0, v1);
        unpack2(acc[r][1], v2, v3);
        v0 += bias[col + 0]; v1 += bias[col + 1];
        v2 += bias[col + 2]; v3 += bias[col + 3];
        if (resid) {
            const float4 rv = *(const float4*)&resid[row * 256 + col];
            v0 += rv.x; v1 += rv.y; v2 += rv.z; v3 += rv.w;
        }
        float4 ov = make_float4(v0, v1, v2, v3);
        *(float4*)&C[row * 256 + col] = ov;
    }
}

// ---------------------------------------------------------------------------
// 4) fused pe-MLP + delta-features + softmax(K) + y reduction.
//    One block per point. 256 threads. Layer-2 GEMM in FFMA2 with x4 j-unroll.
// ---------------------------------------------------------------------------
__global__ __launch_bounds__(256) void attn_kernel(const float* __restrict__ coords,
                                                   const float* __restrict__ w1,
                                                   const float* __restrict__ b1,
                                                   const float* __restrict__ w2,
                                                   const float* __restrict__ b2) {
    __shared__ float sh[16 * 256];       // hidden layer h[k][c]  (16 KB)
    __shared__ float sdf[256 * 17];      // df[c][k], pad 17      (17 KB)
    __shared__ int   sidx[16];
    __shared__ float sdc[16 * 3];

    const int i = blockIdx.x, tid = threadIdx.x;

    if (tid < 16) sidx[tid] = g_idx[i * KNN + tid];
    __syncthreads();
    if (tid < 48) {
        const int k = tid / 3, d = tid - k * 3;
        sdc[tid] = coords[sidx[k] * 3 + d] - coords[i * 3 + d];
    }
    __syncthreads();

    // layer 1: h[k][tid] = relu(dc[k] . w1[:,tid] + b1[tid]); weights in regs
    {
        const float w10 = w1[tid], w11 = w1[256 + tid], w12 = w1[512 + tid];
        const float bb  = b1[tid];
        #pragma unroll
        for (int k = 0; k < 16; k++) {
            float v = fmaf(sdc[k * 3 + 2], w12,
                      fmaf(sdc[k * 3 + 1], w11,
                      fmaf(sdc[k * 3 + 0], w10, bb)));
            sh[k * 256 + tid] = fmaxf(v, 0.0f);
        }
    }
    __syncthreads();

    // layer 2 GEMM: 16(k) x 256(c) x 256(j). thread = (4 c, 4 k) microtile,
    // FFMA2 over c-pairs, j unrolled x4 with LDS.128 h reads.
    const int cg = tid & 63, kg = tid >> 6;
    const int c0 = cg * 4, k0 = kg * 4;
    const ulonglong2 bb2 = *(const ulonglong2*)&b2[c0];
    u64 acc[4][2];                  // [k][c-pair]
    #pragma unroll
    for (int kk = 0; kk < 4; kk++) { acc[kk][0] = bb2.x; acc[kk][1] = bb2.y; }

    const float* hp = &sh[k0 * 256];
    #pragma unroll 2
    for (int j = 0; j < 256; j += 4) {
        const float4 h0 = *(const float4*)&hp[j];
        const float4 h1 = *(const float4*)&hp[256 + j];
        const float4 h2 = *(const float4*)&hp[512 + j];
        const float4 h3 = *(const float4*)&hp[768 + j];
        #pragma unroll
        for (int jj = 0; jj < 4; jj++) {
            const ulonglong2 w = *(const ulonglong2*)&w2[(j + jj) * 256 + c0];
            const float e0 = (jj == 0) ? h0.x : (jj == 1) ? h0.y : (jj == 2) ? h0.z : h0.w;
            const float e1 = (jj == 0) ? h1.x : (jj == 1) ? h1.y : (jj == 2) ? h1.z : h1.w;
            const float e2 = (jj == 0) ? h2.x : (jj == 1) ? h2.y : (jj == 2) ? h2.z : h2.w;
            const float e3 = (jj == 0) ? h3.x : (jj == 1) ? h3.y : (jj == 2) ? h3.z : h3.w;
            const u64 a0 = bcast2(e0), a1 = bcast2(e1), a2 = bcast2(e2), a3 = bcast2(e3);
            fma2(acc[0][0], a0, w.x); fma2(acc[0][1], a0, w.y);
            fma2(acc[1][0], a1, w.x); fma2(acc[1][1], a1, w.y);
            fma2(acc[2][0], a2, w.x); fma2(acc[2][1], a2, w.y);
            fma2(acc[3][0], a3, w.x); fma2(acc[3][1], a3, w.y);
        }
    }

    // delta features -> shared [c][k] (pad 17 for conflict-free reads by k)
    {
        const float4 th = *(const float4*)&g_theta[i * 256 + c0];
        #pragma unroll
        for (int kk = 0; kk < 4; kk++) {
            const int nn = sidx[k0 + kk];
            const float4 ph = *(const float4*)&g_phi[nn * 256 + c0];
            float p0, p1, p2, p3;
            unpack2(acc[kk][0], p0, p1);
            unpack2(acc[kk][1], p2, p3);
            sdf[(c0 + 0) * 17 + k0 + kk] = p0 * (th.x - ph.x + 1.0f) * 0.0625f;
            sdf[(c0 + 1) * 17 + k0 + kk] = p1 * (th.y - ph.y + 1.0f) * 0.0625f;
            sdf[(c0 + 2) * 17 + k0 + kk] = p2 * (th.z - ph.z + 1.0f) * 0.0625f;
            sdf[(c0 + 3) * 17 + k0 + kk] = p3 * (th.w - ph.w + 1.0f) * 0.0625f;
        }
    }
    __syncthreads();

    // softmax over K + weighted sum with g_feats; thread = one channel
    {
        const int c = tid;
        float m = -FLT_MAX;
        #pragma unroll
        for (int k = 0; k < 16; k++) m = fmaxf(m, sdf[c * 17 + k]);
        float e[16];
        float s = 0.0f;
        #pragma unroll
        for (int k = 0; k < 16; k++) { e[k] = __expf(sdf[c * 17 + k] - m); s += e[k]; }
        const float inv = 1.0f / s;
        float a = 0.0f;
        #pragma unroll
        for (int k = 0; k < 16; k++) a = fmaf(e[k], g_gv[sidx[k] * 256 + c], a);
        g_y[i * 256 + c] = a * inv;
    }
}

// ---------------------------------------------------------------------------
extern "C" void kernel_launch(void* const* d_in, const int* in_sizes, int n_in,
                              void* d_out, int out_size) {
    const float* coords  = (const float*)d_in[0];
    const float* feats   = (const float*)d_in[1];
    const float* theta_w = (const float*)d_in[2];
    const float* theta_b = (const float*)d_in[3];
    const float* phi_w   = (const float*)d_in[4];
    const float* phi_b   = (const float*)d_in[5];
    const float* g_w     = (const float*)d_in[6];
    const float* g_b     = (const float*)d_in[7];
    const float* pe_w1   = (const float*)d_in[8];
    const float* pe_b1   = (const float*)d_in[9];
    const float* pe_w2   = (const float*)d_in[10];
    const float* pe_b2   = (const float*)d_in[11];
    const float* W_w     = (const float*)d_in[12];
    const float* W_b     = (const float*)d_in[13];
    float* out = (float*)d_out;

    float *p_theta, *p_phi, *p_gv, *p_y;
    cudaGetSymbolAddress((void**)&p_theta, g_theta);
    cudaGetSymbolAddress((void**)&p_phi,   g_phi);
    cudaGetSymbolAddress((void**)&p_gv,    g_gv);
    cudaGetSymbolAddress((void**)&p_y,     g_y);

    prep_kernel<<<(N_PTS + 255) / 256, 256>>>(coords);
    knn_kernel<<<N_PTS, 256>>>();

    dim3 ggrid(C_CH / 64, N_PTS / 64);
    gemm64_kernel<<<ggrid, 256>>>(feats, theta_w, theta_b, nullptr, p_theta);
    gemm64_kernel<<<ggrid, 256>>>(feats, phi_w,   phi_b,   nullptr, p_phi);
    gemm64_kernel<<<ggrid, 256>>>(feats, g_w,     g_b,     nullptr, p_gv);

    attn_kernel<<<N_PTS, 256>>>(coords, pe_w1, pe_b1, pe_w2, pe_b2);

    gemm64_kernel<<<ggrid, 256>>>(p_y, W_w, W_b, feats, out);
}

// round 9
// speedup vs baseline: 1.1359x; 1.0931x over previous
#include <cuda_runtime.h>
#include <float.h>

// Problem constants (fixed by reference setup_inputs)
#define N_PTS 8192
#define C_CH  256
#define KNN   16

typedef unsigned long long u64;

// ---------------- packed-fp32 (FFMA2) helpers --------------------------------
__device__ __forceinline__ void fma2(u64 &acc, u64 a, u64 b) {
    asm("fma.rn.f32x2 %0, %1, %2, %0;" : "+l"(acc) : "l"(a), "l"(b));
}
__device__ __forceinline__ u64 bcast2(float v) {
    u64 r;
    asm("mov.b64 %0, {%1, %2};" : "=l"(r) : "f"(v), "f"(v));
    return r;
}
__device__ __forceinline__ u64 pack2(float lo, float hi) {
    u64 r;
    asm("mov.b64 %0, {%1, %2};" : "=l"(r) : "f"(lo), "f"(hi));
    return r;
}
__device__ __forceinline__ void unpack2(u64 v, float &lo, float &hi) {
    asm("mov.b64 {%0, %1}, %2;" : "=f"(lo), "=f"(hi) : "l"(v));
}

// ---------------- scratch (device globals; no allocation allowed) ----------
__device__ float4 g_xyzs[N_PTS];            // x,y,z, |p|^2
__device__ int    g_idx[N_PTS * KNN];       // knn indices
__device__ float  g_theta[N_PTS * C_CH];    // feats @ theta_w + b
__device__ float  g_phi  [N_PTS * C_CH];    // feats @ phi_w + b
__device__ float  g_gv   [N_PTS * C_CH];    // feats @ g_w + b
__device__ float  g_y    [N_PTS * C_CH];    // attention output

// ---------------------------------------------------------------------------
// 1) pack coords + squared norms
// ---------------------------------------------------------------------------
__global__ __launch_bounds__(256) void prep_kernel(const float* __restrict__ coords) {
    int i = blockIdx.x * blockDim.x + threadIdx.x;
    if (i < N_PTS) {
        float x = coords[i * 3 + 0], y = coords[i * 3 + 1], z = coords[i * 3 + 2];
        g_xyzs[i] = make_float4(x, y, z, x * x + y * y + z * z);
    }
}

// ---------------------------------------------------------------------------
// 2) KNN (unchanged): one block per query point, 16x argmin w/ cached minima.
// ---------------------------------------------------------------------------
__global__ __launch_bounds__(256) void knn_kernel() {
    __shared__ float sd[N_PTS];       // 32 KB
    __shared__ float wmin[8];
    __shared__ int   warg[8];
    __shared__ int   s_win;

    const int i   = blockIdx.x;
    const int tid = threadIdx.x;
    const float4 q = g_xyzs[i];

    float lmin = FLT_MAX;
    int   larg = 0x7fffffff;
    for (int j = tid; j < N_PTS; j += 256) {
        float4 p = g_xyzs[j];
        float d = q.w + p.w - 2.0f * (q.x * p.x + q.y * p.y + q.z * p.z);
        sd[j] = d;
        if (d < lmin || (d == lmin && j < larg)) { lmin = d; larg = j; }
    }
    __syncthreads();

    const int lane = tid & 31, wid = tid >> 5;
    for (int it = 0; it < KNN; it++) {
        float v = lmin; int a = larg;
        #pragma unroll
        for (int off = 16; off > 0; off >>= 1) {
            float ov = __shfl_down_sync(0xffffffffu, v, off);
            int   oa = __shfl_down_sync(0xffffffffu, a, off);
            if (ov < v || (ov == v && oa < a)) { v = ov; a = oa; }
        }
        if (lane == 0) { wmin[wid] = v; warg[wid] = a; }
        __syncthreads();
        if (tid == 0) {
            float bv = wmin[0]; int ba = warg[0];
            #pragma unroll
            for (int w = 1; w < 8; w++)
                if (wmin[w] < bv || (wmin[w] == bv && warg[w] < ba)) { bv = wmin[w]; ba = warg[w]; }
            s_win = ba;
            g_idx[i * KNN + it] = ba;
        }
        __syncthreads();
        const int wa = s_win;
        if ((wa & 255) == tid) {
            sd[wa] = FLT_MAX;
            lmin = FLT_MAX; larg = 0x7fffffff;
            for (int j = tid; j < N_PTS; j += 256) {
                float d = sd[j];
                if (d < lmin || (d == lmin && j < larg)) { lmin = d; larg = j; }
            }
        }
    }
}

// ---------------------------------------------------------------------------
// 3) C[M,N] = A[M,256] @ B[256,N] + bias (+ residual). 64x64 tile, BK=16.
//    FFMA2 packed over ROW pairs (pack-free from contiguous smem rows);
//    B column reads are conflict-free LDS.128.
// ---------------------------------------------------------------------------
__global__ __launch_bounds__(256) void gemm64_kernel(const float* __restrict__ A,
                                                     const float* __restrict__ B,
                                                     const float* __restrict__ bias,
                                                     const float* __restrict__ resid,
                                                     float* __restrict__ C) {
    __shared__ float As[16][68];   // [k][row], stride 272B (16B-aligned)
    __shared__ float Bs[16][64];   // [k][col]

    const int tid  = threadIdx.x;
    const int row0 = blockIdx.y * 64;
    const int col0 = blockIdx.x * 64;
    const int tx = tid & 15, ty = tid >> 4;
    const int ar = tid >> 2, ak = (tid & 3) * 4;
    const int br = tid >> 4, bc = (tid & 15) * 4;

    u64 acc[2][4];                 // [row-pair][col]
    #pragma unroll
    for (int rp = 0; rp < 2; rp++)
        #pragma unroll
        for (int c = 0; c < 4; c++) acc[rp][c] = 0ull;

    for (int k0 = 0; k0 < 256; k0 += 16) {
        float4 av = *(const float4*)&A[(row0 + ar) * 256 + k0 + ak];
        float4 bv = *(const float4*)&B[(k0 + br) * 256 + col0 + bc];
        As[ak + 0][ar] = av.x; As[ak + 1][ar] = av.y;
        As[ak + 2][ar] = av.z; As[ak + 3][ar] = av.w;
        *(float4*)&Bs[br][bc] = bv;
        __syncthreads();
        #pragma unroll
        for (int kk = 0; kk < 16; kk++) {
            const ulonglong2 a = *(const ulonglong2*)&As[kk][ty * 4];
            const float4 b4 = *(const float4*)&Bs[kk][tx * 4];
            const u64 b0 = bcast2(b4.x), b1 = bcast2(b4.y);
            const u64 b2 = bcast2(b4.z), b3 = bcast2(b4.w);
            fma2(acc[0][0], a.x, b0); fma2(acc[0][1], a.x, b1);
            fma2(acc[0][2], a.x, b2); fma2(acc[0][3], a.x, b3);
            fma2(acc[1][0], a.y, b0); fma2(acc[1][1], a.y, b1);
            fma2(acc[1][2], a.y, b2); fma2(acc[1][3], a.y, b3);
        }
        __syncthreads();
    }

    const int col = col0 + tx * 4;
    const float4 bz = *(const float4*)&bias[col];
    #pragma unroll
    for (int rp = 0; rp < 2; rp++) {
        const int rA = row0 + ty * 4 + rp * 2;
        float l0, h0, l1, h1, l2, h2, l3, h3;
        unpack2(acc[rp][0], l0, h0); unpack2(acc[rp][1], l1, h1);
        unpack2(acc[rp][2], l2, h2); unpack2(acc[rp][3], l3, h3);
        float4 oA = make_float4(l0 + bz.x, l1 + bz.y, l2 + bz.z, l3 + bz.w);
        float4 oB = make_float4(h0 + bz.x, h1 + bz.y, h2 + bz.z, h3 + bz.w);
        if (resid) {
            const float4 rv = *(const float4*)&resid[rA * 256 + col];
            const float4 rw = *(const float4*)&resid[(rA + 1) * 256 + col];
            oA.x += rv.x; oA.y += rv.y; oA.z += rv.z; oA.w += rv.w;
            oB.x += rw.x; oB.y += rw.y; oB.z += rw.z; oB.w += rw.w;
        }
        *(float4*)&C[rA * 256 + col] = oA;
        *(float4*)&C[(rA + 1) * 256 + col] = oB;
    }
}

// ---------------------------------------------------------------------------
// 4) batched attention: 8 points x 128 cols per block (grid 2 x 1024).
//    M=128 rows (point,k), N=128 cols, K=256.
//    - layer-1 hidden generated in-tile per k0 (each value computed once)
//    - FFMA2 packed over row pairs; 8x8 microtile per thread
//    - softmax + y reduction in registers (warp == point, shfl_xor(16))
// ---------------------------------------------------------------------------
__global__ __launch_bounds__(256) void attn_kernel(const float* __restrict__ coords,
                                                   const float* __restrict__ w1,
                                                   const float* __restrict__ b1,
                                                   const float* __restrict__ w2,
                                                   const float* __restrict__ b2) {
    __shared__ float As[16][132];     // [k][row], stride 528B (16B-aligned)
    __shared__ float Bs[16][128];     // [k][col]
    __shared__ float sdc[128 * 3];    // delta coords per row
    __shared__ int   sidx[128];       // neighbor ids per row
    __shared__ float sw1[3 * 256];
    __shared__ float sb1[256];

    const int t  = threadIdx.x;
    const int p0 = blockIdx.y * 8;          // first point of block
    const int cb = blockIdx.x * 128;        // column base
    const int tx = t & 15, ty = t >> 4;

    if (t < 192) ((float4*)sw1)[t] = ((const float4*)w1)[t];
    if (t < 64)  ((float4*)sb1)[t] = ((const float4*)b1)[t];
    if (t < 128) {
        const int p = t >> 4;
        const int nn = g_idx[(p0 + p) * 16 + (t & 15)];
        sidx[t] = nn;
        sdc[t * 3 + 0] = coords[nn * 3 + 0] - coords[(p0 + p) * 3 + 0];
        sdc[t * 3 + 1] = coords[nn * 3 + 1] - coords[(p0 + p) * 3 + 1];
        sdc[t * 3 + 2] = coords[nn * 3 + 2] - coords[(p0 + p) * 3 + 2];
    }
    __syncthreads();

    // dc registers for generation rows (tx*8 .. tx*8+7); fixed across k0
    float dcx[8], dcy[8], dcz[8];
    #pragma unroll
    for (int r = 0; r < 8; r++) {
        dcx[r] = sdc[(tx * 8 + r) * 3 + 0];
        dcy[r] = sdc[(tx * 8 + r) * 3 + 1];
        dcz[r] = sdc[(tx * 8 + r) * 3 + 2];
    }

    // accumulators: 4 row-pairs x 8 cols (cols tx*4+0..3 and 64+tx*4+0..3)
    u64 acc[4][8];
    {
        const float4 bA = *(const float4*)&b2[cb + tx * 4];
        const float4 bB = *(const float4*)&b2[cb + 64 + tx * 4];
        const float bv[8] = {bA.x, bA.y, bA.z, bA.w, bB.x, bB.y, bB.z, bB.w};
        #pragma unroll
        for (int rp = 0; rp < 4; rp++)
            #pragma unroll
            for (int j = 0; j < 8; j++) acc[rp][j] = bcast2(bv[j]);
    }

    const float* w2p = w2 + cb;

    for (int k0 = 0; k0 < 256; k0 += 16) {
        // generate hidden tile: thread handles kk=ty, rows tx*8..+7
        {
            const int kc = k0 + ty;
            const float wx = sw1[kc], wy = sw1[256 + kc], wz = sw1[512 + kc];
            const float bb = sb1[kc];
            float h[8];
            #pragma unroll
            for (int r = 0; r < 8; r++)
                h[r] = fmaxf(fmaf(dcz[r], wz, fmaf(dcy[r], wy, fmaf(dcx[r], wx, bb))), 0.0f);
            *(float4*)&As[ty][tx * 8]     = make_float4(h[0], h[1], h[2], h[3]);
            *(float4*)&As[ty][tx * 8 + 4] = make_float4(h[4], h[5], h[6], h[7]);
        }
        // load w2 tile
        #pragma unroll
        for (int s = 0; s < 2; s++) {
            const int idx = t + s * 256;
            const int kk2 = idx >> 5, cq = (idx & 31) * 4;
            *(float4*)&Bs[kk2][cq] = *(const float4*)&w2p[(k0 + kk2) * 256 + cq];
        }
        __syncthreads();
        #pragma unroll
        for (int kk = 0; kk < 16; kk++) {
            const ulonglong2 a01 = *(const ulonglong2*)&As[kk][ty * 8];
            const ulonglong2 a23 = *(const ulonglong2*)&As[kk][ty * 8 + 4];
            const float4 bA = *(const float4*)&Bs[kk][tx * 4];
            const float4 bB = *(const float4*)&Bs[kk][64 + tx * 4];
            const u64 b0 = bcast2(bA.x), b1v = bcast2(bA.y);
            const u64 b2v = bcast2(bA.z), b3 = bcast2(bA.w);
            const u64 b4 = bcast2(bB.x), b5 = bcast2(bB.y);
            const u64 b6 = bcast2(bB.z), b7 = bcast2(bB.w);
            fma2(acc[0][0], a01.x, b0); fma2(acc[0][1], a01.x, b1v);
            fma2(acc[0][2], a01.x, b2v); fma2(acc[0][3], a01.x, b3);
            fma2(acc[0][4], a01.x, b4); fma2(acc[0][5], a01.x, b5);
            fma2(acc[0][6], a01.x, b6); fma2(acc[0][7], a01.x, b7);
            fma2(acc[1][0], a01.y, b0); fma2(acc[1][1], a01.y, b1v);
            fma2(acc[1][2], a01.y, b2v); fma2(acc[1][3], a01.y, b3);
            fma2(acc[1][4], a01.y, b4); fma2(acc[1][5], a01.y, b5);
            fma2(acc[1][6], a01.y, b6); fma2(acc[1][7], a01.y, b7);
            fma2(acc[2][0], a23.x, b0); fma2(acc[2][1], a23.x, b1v);
            fma2(acc[2][2], a23.x, b2v); fma2(acc[2][3], a23.x, b3);
            fma2(acc[2][4], a23.x, b4); fma2(acc[2][5], a23.x, b5);
            fma2(acc[2][6], a23.x, b6); fma2(acc[2][7], a23.x, b7);
            fma2(acc[3][0], a23.y, b0); fma2(acc[3][1], a23.y, b1v);
            fma2(acc[3][2], a23.y, b2v); fma2(acc[3][3], a23.y, b3);
            fma2(acc[3][4], a23.y, b4); fma2(acc[3][5], a23.y, b5);
            fma2(acc[3][6], a23.y, b6); fma2(acc[3][7], a23.y, b7);
        }
        __syncthreads();
    }

    // ---------------- epilogue: df -> softmax(K) -> y, all in registers ----
    // warp w owns point p0+w (rows 16w..16w+15). lanes 0-15: k 0-7; 16-31: k 8-15.
    const int w = t >> 5;
    const int i = p0 + w;
    const int half = (t >> 4) & 1;
    const int kbase = half * 8;

    float th[8];
    {
        const float4 tA = *(const float4*)&g_theta[i * 256 + cb + tx * 4];
        const float4 tB = *(const float4*)&g_theta[i * 256 + cb + 64 + tx * 4];
        th[0] = tA.x; th[1] = tA.y; th[2] = tA.z; th[3] = tA.w;
        th[4] = tB.x; th[5] = tB.y; th[6] = tB.z; th[7] = tB.w;
    }

    float mx[8];
    #pragma unroll
    for (int j = 0; j < 8; j++) mx[j] = -FLT_MAX;

    // pass 1: delta features (in place), track max over own 8 k
    #pragma unroll
    for (int rp = 0; rp < 4; rp++) {
        const int nl = sidx[w * 16 + kbase + rp * 2];
        const int nh = sidx[w * 16 + kbase + rp * 2 + 1];
        const float4 lA = *(const float4*)&g_phi[nl * 256 + cb + tx * 4];
        const float4 lB = *(const float4*)&g_phi[nl * 256 + cb + 64 + tx * 4];
        const float4 hA = *(const float4*)&g_phi[nh * 256 + cb + tx * 4];
        const float4 hB = *(const float4*)&g_phi[nh * 256 + cb + 64 + tx * 4];
        const float pl[8] = {lA.x, lA.y, lA.z, lA.w, lB.x, lB.y, lB.z, lB.w};
        const float ph[8] = {hA.x, hA.y, hA.z, hA.w, hB.x, hB.y, hB.z, hB.w};
        #pragma unroll
        for (int j = 0; j < 8; j++) {
            float lo, hi;
            unpack2(acc[rp][j], lo, hi);
            lo = lo * (th[j] - pl[j] + 1.0f) * 0.0625f;
            hi = hi * (th[j] - ph[j] + 1.0f) * 0.0625f;
            mx[j] = fmaxf(mx[j], fmaxf(lo, hi));
            acc[rp][j] = pack2(lo, hi);
        }
    }
    #pragma unroll
    for (int j = 0; j < 8; j++)
        mx[j] = fmaxf(mx[j], __shfl_xor_sync(0xffffffffu, mx[j], 16));

    float ssum[8], gac[8];
    #pragma unroll
    for (int j = 0; j < 8; j++) { ssum[j] = 0.0f; gac[j] = 0.0f; }

    // pass 2: exp + weighted g accumulation
    #pragma unroll
    for (int rp = 0; rp < 4; rp++) {
        const int nl = sidx[w * 16 + kbase + rp * 2];
        const int nh = sidx[w * 16 + kbase + rp * 2 + 1];
        const float4 lA = *(const float4*)&g_gv[nl * 256 + cb + tx * 4];
        const float4 lB = *(const float4*)&g_gv[nl * 256 + cb + 64 + tx * 4];
        const float4 hA = *(const float4*)&g_gv[nh * 256 + cb + tx * 4];
        const float4 hB = *(const float4*)&g_gv[nh * 256 + cb + 64 + tx * 4];
        const float gl[8] = {lA.x, lA.y, lA.z, lA.w, lB.x, lB.y, lB.z, lB.w};
        const float gh[8] = {hA.x, hA.y, hA.z, hA.w, hB.x, hB.y, hB.z, hB.w};
        #pragma unroll
        for (int j = 0; j < 8; j++) {
            float lo, hi;
            unpack2(acc[rp][j], lo, hi);
            const float el = __expf(lo - mx[j]);
            const float eh = __expf(hi - mx[j]);
            ssum[j] += el + eh;
            gac[j] = fmaf(el, gl[j], fmaf(eh, gh[j], gac[j]));
        }
    }
    #pragma unroll
    for (int j = 0; j < 8; j++) {
        ssum[j] += __shfl_xor_sync(0xffffffffu, ssum[j], 16);
        gac[j]  += __shfl_xor_sync(0xffffffffu, gac[j], 16);
    }

    if (half == 0) {
        float4 oA = make_float4(gac[0] / ssum[0], gac[1] / ssum[1],
                                gac[2] / ssum[2], gac[3] / ssum[3]);
        float4 oB = make_float4(gac[4] / ssum[4], gac[5] / ssum[5],
                                gac[6] / ssum[6], gac[7] / ssum[7]);
        *(float4*)&g_y[i * 256 + cb + tx * 4] = oA;
        *(float4*)&g_y[i * 256 + cb + 64 + tx * 4] = oB;
    }
}

// ---------------------------------------------------------------------------
extern "C" void kernel_launch(void* const* d_in, const int* in_sizes, int n_in,
                              void* d_out, int out_size) {
    const float* coords  = (const float*)d_in[0];
    const float* feats   = (const float*)d_in[1];
    const float* theta_w = (const float*)d_in[2];
    const float* theta_b = (const float*)d_in[3];
    const float* phi_w   = (const float*)d_in[4];
    const float* phi_b   = (const float*)d_in[5];
    const float* g_w     = (const float*)d_in[6];
    const float* g_b     = (const float*)d_in[7];
    const float* pe_w1   = (const float*)d_in[8];
    const float* pe_b1   = (const float*)d_in[9];
    const float* pe_w2   = (const float*)d_in[10];
    const float* pe_b2   = (const float*)d_in[11];
    const float* W_w     = (const float*)d_in[12];
    const float* W_b     = (const float*)d_in[13];
    float* out = (float*)d_out;

    float *p_theta, *p_phi, *p_gv, *p_y;
    cudaGetSymbolAddress((void**)&p_theta, g_theta);
    cudaGetSymbolAddress((void**)&p_phi,   g_phi);
    cudaGetSymbolAddress((void**)&p_gv,    g_gv);
    cudaGetSymbolAddress((void**)&p_y,     g_y);

    prep_kernel<<<(N_PTS + 255) / 256, 256>>>(coords);
    knn_kernel<<<N_PTS, 256>>>();

    dim3 ggrid(C_CH / 64, N_PTS / 64);
    gemm64_kernel<<<ggrid, 256>>>(feats, theta_w, theta_b, nullptr, p_theta);
    gemm64_kernel<<<ggrid, 256>>>(feats, phi_w,   phi_b,   nullptr, p_phi);
    gemm64_kernel<<<ggrid, 256>>>(feats, g_w,     g_b,     nullptr, p_gv);

    dim3 agrid(2, N_PTS / 8);
    attn_kernel<<<agrid, 256>>>(coords, pe_w1, pe_b1, pe_w2, pe_b2);

    gemm64_kernel<<<ggrid, 256>>>(p_y, W_w, W_b, feats, out);
}